// round 13
// baseline (speedup 1.0000x reference)
#include <cuda_runtime.h>
#include <cuda_fp16.h>
#include <cuda_bf16.h>
#include <cstdint>

#define HINGES 1024
#define TILE_F4 512            // float4 per tile = 8 KB
#define THREADS 256

// out(x) = P + S*(x - c*delta), c = ceil(x/delta), t = clamp(c+511, 0, 1023).
// (P,S) built in fp32 replicating reference clamp+wrap gather semantics,
// stored fp16 (P anchored at x0 = c*delta -> output-relative fp16 error).
// Tails via exact fp32 selects.
__device__ __forceinline__ float adact1(float xv, const __half2* __restrict__ tabh,
                                        float r, float s, float delta, float inv_delta,
                                        float a0, float aL) {
    float q  = __fmul_rn(xv, inv_delta);
    float cf = ceilf(q);
    int   c  = (int)cf;
    int   t  = min(max(c + 511, 0), HINGES - 1);
    float2 ps = __half22float2(tabh[t]);     // one LDS.32
    float xa = __fmaf_rn(-delta, cf, xv);    // x - c*delta
    float v  = __fmaf_rn(ps.y, xa, ps.x);
    v = (xv < r) ? a0 : v;
    v = (xv > s) ? aL : v;
    return v;
}

__device__ __forceinline__ unsigned int smem_u32(const void* p) {
    unsigned int a;
    asm("{ .reg .u64 t; cvta.to.shared.u64 t, %1; cvt.u32.u64 %0, t; }"
        : "=r"(a) : "l"(p));
    return a;
}

__global__ __launch_bounds__(THREADS, 8)
void adact_kernel(const float4* __restrict__ x,
                  const float*  __restrict__ ns,
                  const float*  __restrict__ a,
                  float4* __restrict__ out, int ntiles) {
    __shared__ __half2 tabh[HINGES];                 // 4 KB (P,S) per bin
    __shared__ __align__(16) float4 buf[2][TILE_F4]; // 2 x 8 KB staging

    const float r     = ns[0];
    const float s     = ns[HINGES - 1];
    const float a0    = a[0];
    const float aL    = a[HINGES - 1];
    const float delta = __fadd_rn(ns[1], -ns[0]);
    const float inv_delta = __fdiv_rn(1.0f, delta);

    // Build anchored-affine table (reference clamp+wrap logic, fp32).
    #pragma unroll
    for (int t = threadIdx.x; t < HINGES; t += THREADS) {
        int c  = t - 511;
        int m1 = max(c - 1, 0);
        m1 = min(m1, HINGES - 1);
        int m2 = c;
        if (m2 >= HINGES) m2 = HINGES - 1;
        if (m2 < 0)       m2 += HINGES;
        m2 = min(max(m2, 0), HINGES - 1);

        float ns1 = ns[m1], ns2 = ns[m2];
        float a1  = a[m1],  a2  = a[m2];
        float denom = __fadd_rn(ns2, -ns1);
        denom = (denom == 0.0f) ? 1.0f : denom;

        float x0 = __fmul_rn((float)c, delta);
        float w1 = __fdiv_rn(__fadd_rn(ns2, -x0), denom);
        float w2 = __fdiv_rn(__fadd_rn(x0, -ns1), denom);
        float P  = __fadd_rn(__fmul_rn(w1, a1), __fmul_rn(w2, a2));
        float S  = __fdiv_rn(__fadd_rn(a2, -a1), denom);
        tabh[t] = __floats2half2_rn(P, S);
    }
    __syncthreads();

    const int tid = threadIdx.x;
    int stage = 0;

    // Tile loop: loads stay LDG.128->regs; stores go smem -> bulk-async
    // (cp.async.bulk reads smem via the async proxy and writes L2 directly:
    // no per-warp STG issue cost, no L1 store wavefronts).
    for (int tb = blockIdx.x; tb < ntiles; tb += gridDim.x, stage ^= 1) {
        // Ensure the bulk store that last read buf[stage] (2 iters ago) is done.
        if (tid == 0)
            asm volatile("cp.async.bulk.wait_group.read 1;" ::: "memory");
        __syncthreads();

        const int base = tb * TILE_F4;
        float4 v0 = __ldcs(&x[base + tid]);
        float4 v1 = __ldcs(&x[base + tid + 256]);

        float4 o0, o1;
        o0.x = adact1(v0.x, tabh, r, s, delta, inv_delta, a0, aL);
        o0.y = adact1(v0.y, tabh, r, s, delta, inv_delta, a0, aL);
        o0.z = adact1(v0.z, tabh, r, s, delta, inv_delta, a0, aL);
        o0.w = adact1(v0.w, tabh, r, s, delta, inv_delta, a0, aL);
        o1.x = adact1(v1.x, tabh, r, s, delta, inv_delta, a0, aL);
        o1.y = adact1(v1.y, tabh, r, s, delta, inv_delta, a0, aL);
        o1.z = adact1(v1.z, tabh, r, s, delta, inv_delta, a0, aL);
        o1.w = adact1(v1.w, tabh, r, s, delta, inv_delta, a0, aL);

        buf[stage][tid]       = o0;   // STS.128
        buf[stage][tid + 256] = o1;   // STS.128
        __syncthreads();

        if (tid == 0) {
            asm volatile("fence.proxy.async.shared::cta;" ::: "memory");
            unsigned int src = smem_u32(&buf[stage][0]);
            asm volatile(
                "cp.async.bulk.global.shared::cta.bulk_group [%0], [%1], %2;"
                :: "l"(&out[base]), "r"(src), "n"(TILE_F4 * 16) : "memory");
            asm volatile("cp.async.bulk.commit_group;" ::: "memory");
        }
    }

    // Drain outstanding bulk stores before exit.
    if (tid == 0)
        asm volatile("cp.async.bulk.wait_group.read 0;" ::: "memory");
}

extern "C" void kernel_launch(void* const* d_in, const int* in_sizes, int n_in,
                              void* d_out, int out_size) {
    const float* x  = (const float*)d_in[0];
    const float* ns = (const float*)d_in[1];
    const float* a  = (const float*)d_in[2];
    float* out = (float*)d_out;

    int n  = in_sizes[0];
    int n4 = n >> 2;
    int ntiles = n4 / TILE_F4;               // 4096*8192/4/512 = 16384 exactly

    int blocks = 148 * 8;                    // one wave @ 8 CTAs/SM
    if (blocks > ntiles) blocks = ntiles;

    adact_kernel<<<blocks, THREADS>>>((const float4*)x, ns, a, (float4*)out, ntiles);
}

// round 14
// speedup vs baseline: 1.0493x; 1.0493x over previous
#include <cuda_runtime.h>
#include <cuda_fp16.h>
#include <cuda_bf16.h>
#include <cstdint>

#define HINGES 1024
#define TBINS  2048   // half-bins: c2 = ceil(x * 2/delta), t = c2 + 1023

// Half-bin table: tail boundaries r = -1023*h, s = +1023*h (h = delta/2) are
// exact half-bin edges, so every half-bin is uniformly tail or in-range and
// the per-element tail selects disappear:
//   t = clamp(ceil(x/h) + 1023, 0, 2047);  out = P[t] + S[t]*(x - (t-1023)*h)
// t=0 -> (a0,0), t=2047 -> (aL,0); in-range bins share the parent full bin's
// affine law, P anchored at x0 = c2*h (fp32 build, fp16 store -> output-
// relative rounding ~3e-4, same as the passing 51.5us kernel).
__device__ __forceinline__ float adact1(float xv, const __half2* __restrict__ tabh,
                                        float h, float inv_h) {
    float q  = __fmul_rn(xv, inv_h);
    float cf = ceilf(q);
    int   t  = min(max((int)cf + 1023, 0), TBINS - 1);
    float2 ps = __half22float2(tabh[t]);     // one LDS.32
    float xa = __fmaf_rn(-h, cf, xv);        // x - c2*h (tails: S=0, value unused)
    return __fmaf_rn(ps.y, xa, ps.x);
}

__global__ __launch_bounds__(256, 8)
void adact_kernel(const float4* __restrict__ x,
                  const float*  __restrict__ ns,
                  const float*  __restrict__ a,
                  float4* __restrict__ out, int n4) {
    __shared__ __half2 tabh[TBINS];          // 8 KB (P,S) per half-bin

    const float a0    = a[0];
    const float aL    = a[HINGES - 1];
    const float delta = __fadd_rn(ns[1], -ns[0]);
    const float h     = __fmul_rn(delta, 0.5f);
    const float inv_h = __fdiv_rn(1.0f, h);

    // Build half-bin table (reference clamp+wrap gather logic per parent bin).
    #pragma unroll
    for (int t = threadIdx.x; t < TBINS; t += 256) {
        int c2 = t - 1023;                   // c2 = ceil(x/h) for this half-bin
        float P, S;
        if (c2 <= -1023) {                   // x <= r  (x == r: interp == a0 too)
            P = a0; S = 0.0f;
        } else if (c2 >= 1024) {             // x > s
            P = aL; S = 0.0f;
        } else {
            int c  = ((c2 + 2049) >> 1) - 1024;   // parent bin: c = ceil(c2/2)
            int m1 = max(c - 1, 0);
            m1 = min(m1, HINGES - 1);
            int m2 = c;
            if (m2 >= HINGES) m2 = HINGES - 1;    // torch upper clamp
            if (m2 < 0)       m2 += HINGES;       // torch negative wrap
            m2 = min(max(m2, 0), HINGES - 1);

            float ns1 = ns[m1], ns2 = ns[m2];
            float a1  = a[m1],  a2  = a[m2];
            float denom = __fadd_rn(ns2, -ns1);
            denom = (denom == 0.0f) ? 1.0f : denom;

            float x0 = __fmul_rn((float)c2, h);   // half-bin anchor
            float w1 = __fdiv_rn(__fadd_rn(ns2, -x0), denom);
            float w2 = __fdiv_rn(__fadd_rn(x0, -ns1), denom);
            P = __fadd_rn(__fmul_rn(w1, a1), __fmul_rn(w2, a2));
            S = __fdiv_rn(__fadd_rn(a2, -a1), denom);
        }
        tabh[t] = __floats2half2_rn(P, S);
    }
    __syncthreads();

    // Winner config: 4 front-batched LDG.128s, 32 regs, 64 warps/SM.
    const int stride = gridDim.x * 256;
    int idx = blockIdx.x * 256 + threadIdx.x;

    for (; idx + 3 * stride < n4; idx += 4 * stride) {
        float4 v0 = __ldcs(&x[idx]);
        float4 v1 = __ldcs(&x[idx + stride]);
        float4 v2 = __ldcs(&x[idx + 2 * stride]);
        float4 v3 = __ldcs(&x[idx + 3 * stride]);

        float4 o0, o1, o2, o3;
        o0.x = adact1(v0.x, tabh, h, inv_h);
        o0.y = adact1(v0.y, tabh, h, inv_h);
        o0.z = adact1(v0.z, tabh, h, inv_h);
        o0.w = adact1(v0.w, tabh, h, inv_h);
        o1.x = adact1(v1.x, tabh, h, inv_h);
        o1.y = adact1(v1.y, tabh, h, inv_h);
        o1.z = adact1(v1.z, tabh, h, inv_h);
        o1.w = adact1(v1.w, tabh, h, inv_h);
        o2.x = adact1(v2.x, tabh, h, inv_h);
        o2.y = adact1(v2.y, tabh, h, inv_h);
        o2.z = adact1(v2.z, tabh, h, inv_h);
        o2.w = adact1(v2.w, tabh, h, inv_h);
        o3.x = adact1(v3.x, tabh, h, inv_h);
        o3.y = adact1(v3.y, tabh, h, inv_h);
        o3.z = adact1(v3.z, tabh, h, inv_h);
        o3.w = adact1(v3.w, tabh, h, inv_h);

        __stcs(&out[idx],              o0);
        __stcs(&out[idx + stride],     o1);
        __stcs(&out[idx + 2 * stride], o2);
        __stcs(&out[idx + 3 * stride], o3);
    }
    for (; idx < n4; idx += stride) {
        float4 v = __ldcs(&x[idx]);
        float4 o;
        o.x = adact1(v.x, tabh, h, inv_h);
        o.y = adact1(v.y, tabh, h, inv_h);
        o.z = adact1(v.z, tabh, h, inv_h);
        o.w = adact1(v.w, tabh, h, inv_h);
        __stcs(&out[idx], o);
    }
}

extern "C" void kernel_launch(void* const* d_in, const int* in_sizes, int n_in,
                              void* d_out, int out_size) {
    const float* x  = (const float*)d_in[0];
    const float* ns = (const float*)d_in[1];
    const float* a  = (const float*)d_in[2];
    float* out = (float*)d_out;

    int n  = in_sizes[0];
    int n4 = n >> 2;

    int blocks = (n4 + 255) / 256;
    const int max_blocks = 148 * 8;          // one wave @ 8 CTAs/SM
    if (blocks > max_blocks) blocks = max_blocks;

    adact_kernel<<<blocks, 256>>>((const float4*)x, ns, a, (float4*)out, n4);
}